// round 13
// baseline (speedup 1.0000x reference)
#include <cuda_runtime.h>
#include <cuda_fp16.h>
#include <cstdint>

#define SEQ 2048
#define HDIM 64
#define NBH 32
#define QT 64
#define KT 32
#define NTILES 64
#define NTH 64
// 0.125 * log2(e): scores computed directly in log2 domain
#define QSCALE2 0.18033688011112042f

// ---- kernel A smem: 2 KV buffers of 8KB; Q staging 8KB ----
#define BUFS 8192
#define KH_O 0
#define VH_O 4096
#define QH_A 16384
#define SMEM_A 24576
// ---- kernel B smem: 2 K buffers of 4KB; Q staging 8KB ----
#define QH_B 8192
#define SMEM_B 16384

__device__ __half g_kh[NBH*SEQ*HDIM];
__device__ __half g_vh[NBH*SEQ*HDIM];
__device__ float  g_inv[NBH*SEQ];

__device__ __forceinline__ uint32_t s2u(const void* p) {
    return (uint32_t)__cvta_generic_to_shared(p);
}
__device__ __forceinline__ void cp16(uint32_t dst, const void* src) {
    asm volatile("cp.async.cg.shared.global [%0], [%1], 16;" :: "r"(dst), "l"(src));
}
__device__ __forceinline__ void ldmx4(uint32_t* r, uint32_t a) {
    asm volatile("ldmatrix.sync.aligned.m8n8.x4.shared.b16 {%0,%1,%2,%3}, [%4];"
                 : "=r"(r[0]),"=r"(r[1]),"=r"(r[2]),"=r"(r[3]) : "r"(a));
}
__device__ __forceinline__ void ldmx4t(uint32_t* r, uint32_t a) {
    asm volatile("ldmatrix.sync.aligned.m8n8.x4.trans.shared.b16 {%0,%1,%2,%3}, [%4];"
                 : "=r"(r[0]),"=r"(r[1]),"=r"(r[2]),"=r"(r[3]) : "r"(a));
}
__device__ __forceinline__ void mma(float* c, const uint32_t* a, uint32_t b0, uint32_t b1) {
    asm volatile("mma.sync.aligned.m16n8k16.row.col.f32.f16.f16.f32 "
                 "{%0,%1,%2,%3}, {%4,%5,%6,%7}, {%8,%9}, {%0,%1,%2,%3};"
                 : "+f"(c[0]),"+f"(c[1]),"+f"(c[2]),"+f"(c[3])
                 : "r"(a[0]),"r"(a[1]),"r"(a[2]),"r"(a[3]), "r"(b0),"r"(b1));
}
__device__ __forceinline__ uint32_t h2pk(float a, float b) {
    uint32_t r;
    asm("cvt.rn.f16x2.f32 %0, %1, %2;" : "=r"(r) : "f"(b), "f"(a));
    return r;
}
__device__ __forceinline__ float ex2(float x) {
    float r;
    asm("ex2.approx.f32 %0, %1;" : "=f"(r) : "f"(x));
    return r;
}
__device__ __forceinline__ void stg_cs2(float* p, float a, float b) {
    asm volatile("st.global.cs.v2.f32 [%0], {%1,%2};" :: "l"(p), "f"(a), "f"(b) : "memory");
}
// swizzled byte offset within a [rows x 128B] fp16 tile (16B unit c = 0..7)
__device__ __forceinline__ uint32_t swz(int row, int c) {
    return (uint32_t)row * 128u + (uint32_t)(((c ^ (row & 7)) & 7) << 4);
}

// load K+V fp16 for one 32-key tile (8KB, 512 cp16, 8 each)
__device__ __forceinline__ void ldtileKV(uint32_t sb, int buf, int tile, int bh, int tid) {
    size_t base = ((size_t)bh * SEQ + (size_t)tile * KT) * HDIM;
    uint32_t bo = sb + (uint32_t)buf * BUFS;
    #pragma unroll
    for (int m = 0; m < 8; m++) {
        int e = tid + (m & 3) * NTH;
        int row = e >> 3, c = e & 7;
        const __half* s = (m < 4) ? g_kh : g_vh;
        cp16(bo + (uint32_t)(m >> 2) * 4096u + swz(row, c),
             s + base + row * HDIM + c * 8);
    }
}
// load K only into 4KB buffer (256 cp16, 4 each)
__device__ __forceinline__ void ldtileK(uint32_t sb, int buf, int tile, int bh, int tid) {
    size_t base = ((size_t)bh * SEQ + (size_t)tile * KT) * HDIM;
    uint32_t bo = sb + (uint32_t)buf * 4096u;
    #pragma unroll
    for (int m = 0; m < 4; m++) {
        int e = tid + m * NTH;
        int row = e >> 3, c = e & 7;
        cp16(bo + swz(row, c), g_kh + base + row * HDIM + c * 8);
    }
}
// stage 64 rows of Q (scaled fp16) into smem at offset qo
__device__ __forceinline__ void stageQ(char* smem, uint32_t qo,
                                       const float* __restrict__ Qg,
                                       int bh, int q0, int tid) {
    #pragma unroll
    for (int i = 0; i < 8; i++) {
        int gid = tid + i * NTH;
        int row = gid >> 3, c = gid & 7;
        const float* qp = Qg + ((size_t)(bh * SEQ + q0 + row)) * HDIM + c * 8;
        float4 f0 = *(const float4*)qp, f1 = *(const float4*)(qp + 4);
        uint32_t h[4];
        h[0] = h2pk(f0.x * QSCALE2, f0.y * QSCALE2);
        h[1] = h2pk(f0.z * QSCALE2, f0.w * QSCALE2);
        h[2] = h2pk(f1.x * QSCALE2, f1.y * QSCALE2);
        h[3] = h2pk(f1.z * QSCALE2, f1.w * QSCALE2);
        *(uint4*)(smem + qo + swz(row, c)) = make_uint4(h[0], h[1], h[2], h[3]);
    }
}

__global__ void prep_kv(const float4* __restrict__ K4, const float4* __restrict__ V4) {
    const int n4 = NBH * SEQ * HDIM / 4;
    uint2* kh = (uint2*)g_kh;
    uint2* vh = (uint2*)g_vh;
    for (int i = blockIdx.x * blockDim.x + threadIdx.x; i < n4; i += gridDim.x * blockDim.x) {
        float4 k = K4[i];
        kh[i] = make_uint2(h2pk(k.x, k.y), h2pk(k.z, k.w));
        float4 v = V4[i];
        vh[i] = make_uint2(h2pk(v.x, v.y), h2pk(v.z, v.w));
    }
}

// =============== KERNEL A: O + rowsum -> inv ===============
__global__ __launch_bounds__(NTH, 6)
void attn_p1(const float* __restrict__ Qg, float* __restrict__ Og) {
    extern __shared__ char smem[];
    const int tid = threadIdx.x, wid = tid >> 5, L = tid & 31;
    const int bh = blockIdx.y, q0 = blockIdx.x * QT;
    const uint32_t sb = s2u(smem);

    ldtileKV(sb, 0, 0, bh, tid);
    asm volatile("cp.async.commit_group;" ::: "memory");
    stageQ(smem, QH_A, Qg, bh, q0, tid);
    __syncthreads();

    const int g = L >> 2, i2 = (L & 3) * 2;
    const int qc_sel  = L >> 4;
    const int rk_base = (L & 7) + ((L >> 4) << 3);
    const int ck_sel  = (L >> 3) & 1;
    const int rv_base = (L & 7) + (((L >> 3) & 1) << 3);
    const int cv_sel  = L >> 4;

    // Q A-fragments in registers: [mt][ks], reused by all 64 tiles
    uint32_t qf[2][4][4];
    #pragma unroll
    for (int mt = 0; mt < 2; mt++) {
        int qrow = wid * 32 + mt * 16 + (L & 7) + (((L >> 3) & 1) << 3);
        #pragma unroll
        for (int ks = 0; ks < 4; ks++)
            ldmx4(qf[mt][ks], sb + QH_A + swz(qrow, 2 * ks + qc_sel));
    }

    float o[2][8][4];
    #pragma unroll
    for (int mt = 0; mt < 2; mt++)
        #pragma unroll
        for (int i = 0; i < 8; i++)
            #pragma unroll
            for (int j = 0; j < 4; j++) o[mt][i][j] = 0.f;
    float rs[2][2] = {{0.f, 0.f}, {0.f, 0.f}};

    for (int t = 0; t < NTILES; t++) {
        if (t + 1 < NTILES) {
            ldtileKV(sb, (t + 1) & 1, t + 1, bh, tid);
            asm volatile("cp.async.commit_group;" ::: "memory");
            asm volatile("cp.async.wait_group 1;" ::: "memory");
        } else {
            asm volatile("cp.async.wait_group 0;" ::: "memory");
        }
        __syncthreads();
        const uint32_t kb = sb + (uint32_t)(t & 1) * BUFS;

        float s[2][4][4];
        #pragma unroll
        for (int mt = 0; mt < 2; mt++)
            #pragma unroll
            for (int i = 0; i < 4; i++)
                #pragma unroll
                for (int j = 0; j < 4; j++) s[mt][i][j] = 0.f;

        #pragma unroll
        for (int ks = 0; ks < 4; ks++) {
            int ck = 2 * ks + ck_sel;
            #pragma unroll
            for (int ntp = 0; ntp < 2; ntp++) {
                uint32_t bf[4];
                ldmx4(bf, kb + KH_O + swz(ntp * 16 + rk_base, ck));
                #pragma unroll
                for (int mt = 0; mt < 2; mt++) {
                    mma(s[mt][2*ntp],   qf[mt][ks], bf[0], bf[1]);
                    mma(s[mt][2*ntp+1], qf[mt][ks], bf[2], bf[3]);
                }
            }
        }

        uint32_t pah[2][2][4];
        #pragma unroll
        for (int mt = 0; mt < 2; mt++)
            #pragma unroll
            for (int nt = 0; nt < 4; nt++) {
                float p0 = ex2(s[mt][nt][0]), p1 = ex2(s[mt][nt][1]);
                float p2 = ex2(s[mt][nt][2]), p3 = ex2(s[mt][nt][3]);
                rs[mt][0] += p0 + p1; rs[mt][1] += p2 + p3;
                pah[mt][nt >> 1][(nt & 1) * 2 + 0] = h2pk(p0, p1);
                pah[mt][nt >> 1][(nt & 1) * 2 + 1] = h2pk(p2, p3);
            }

        #pragma unroll
        for (int ks = 0; ks < 2; ks++) {
            int rv = ks * 16 + rv_base;
            #pragma unroll
            for (int dp = 0; dp < 4; dp++) {
                uint32_t vh[4];
                ldmx4t(vh, kb + VH_O + swz(rv, dp * 2 + cv_sel));
                #pragma unroll
                for (int mt = 0; mt < 2; mt++) {
                    mma(o[mt][2*dp],   pah[mt][ks], vh[0], vh[1]);
                    mma(o[mt][2*dp+1], pah[mt][ks], vh[2], vh[3]);
                }
            }
        }
        __syncthreads();
    }

    float inv[2][2];
    #pragma unroll
    for (int mt = 0; mt < 2; mt++)
        #pragma unroll
        for (int j = 0; j < 2; j++) {
            float r = rs[mt][j];
            r += __shfl_xor_sync(0xFFFFFFFFu, r, 1);
            r += __shfl_xor_sync(0xFFFFFFFFu, r, 2);
            inv[mt][j] = 1.0f / r;
        }

    #pragma unroll
    for (int mt = 0; mt < 2; mt++) {
        if ((L & 3) == 0) {
            g_inv[bh * SEQ + q0 + wid * 32 + mt * 16 + g]     = inv[mt][0];
            g_inv[bh * SEQ + q0 + wid * 32 + mt * 16 + 8 + g] = inv[mt][1];
        }
        float* ob = Og + ((size_t)(bh * SEQ + q0 + wid * 32 + mt * 16)) * HDIM;
        #pragma unroll
        for (int nt = 0; nt < 8; nt++) {
            *(float2*)(ob + (size_t)g * HDIM + nt * 8 + i2) =
                make_float2(o[mt][nt][0] * inv[mt][0], o[mt][nt][1] * inv[mt][0]);
            *(float2*)(ob + (size_t)(8 + g) * HDIM + nt * 8 + i2) =
                make_float2(o[mt][nt][2] * inv[mt][1], o[mt][nt][3] * inv[mt][1]);
        }
    }
}

// =============== KERNEL B: recompute scores, store normalized P ===============
__global__ __launch_bounds__(NTH, 10)
void attn_p2(const float* __restrict__ Qg, float* __restrict__ Pg) {
    extern __shared__ char smem[];
    const int tid = threadIdx.x, wid = tid >> 5, L = tid & 31;
    const int bh = blockIdx.y, q0 = blockIdx.x * QT;
    const uint32_t sb = s2u(smem);

    ldtileK(sb, 0, 0, bh, tid);
    asm volatile("cp.async.commit_group;" ::: "memory");
    stageQ(smem, QH_B, Qg, bh, q0, tid);
    __syncthreads();

    const int g = L >> 2, i2 = (L & 3) * 2;
    const int qc_sel  = L >> 4;
    const int rk_base = (L & 7) + ((L >> 4) << 3);
    const int ck_sel  = (L >> 3) & 1;

    uint32_t qf[2][4][4];
    #pragma unroll
    for (int mt = 0; mt < 2; mt++) {
        int qrow = wid * 32 + mt * 16 + (L & 7) + (((L >> 3) & 1) << 3);
        #pragma unroll
        for (int ks = 0; ks < 4; ks++)
            ldmx4(qf[mt][ks], sb + QH_B + swz(qrow, 2 * ks + qc_sel));
    }

    float inv[2][2];
    #pragma unroll
    for (int mt = 0; mt < 2; mt++) {
        inv[mt][0] = g_inv[bh * SEQ + q0 + wid * 32 + mt * 16 + g];
        inv[mt][1] = g_inv[bh * SEQ + q0 + wid * 32 + mt * 16 + 8 + g];
    }

    for (int t = 0; t < NTILES; t++) {
        if (t + 1 < NTILES) {
            ldtileK(sb, (t + 1) & 1, t + 1, bh, tid);
            asm volatile("cp.async.commit_group;" ::: "memory");
            asm volatile("cp.async.wait_group 1;" ::: "memory");
        } else {
            asm volatile("cp.async.wait_group 0;" ::: "memory");
        }
        __syncthreads();
        const uint32_t kb = sb + (uint32_t)(t & 1) * 4096u;

        float s[2][4][4];
        #pragma unroll
        for (int mt = 0; mt < 2; mt++)
            #pragma unroll
            for (int i = 0; i < 4; i++)
                #pragma unroll
                for (int j = 0; j < 4; j++) s[mt][i][j] = 0.f;

        #pragma unroll
        for (int ks = 0; ks < 4; ks++) {
            int ck = 2 * ks + ck_sel;
            #pragma unroll
            for (int ntp = 0; ntp < 2; ntp++) {
                uint32_t bf[4];
                ldmx4(bf, kb + swz(ntp * 16 + rk_base, ck));
                #pragma unroll
                for (int mt = 0; mt < 2; mt++) {
                    mma(s[mt][2*ntp],   qf[mt][ks], bf[0], bf[1]);
                    mma(s[mt][2*ntp+1], qf[mt][ks], bf[2], bf[3]);
                }
            }
        }

        #pragma unroll
        for (int mt = 0; mt < 2; mt++) {
            float* pt = Pg + ((size_t)(bh * SEQ + q0 + wid * 32 + mt * 16)) * SEQ
                        + (size_t)t * KT;
            #pragma unroll
            for (int nt = 0; nt < 4; nt++) {
                float p0 = ex2(s[mt][nt][0]) * inv[mt][0];
                float p1 = ex2(s[mt][nt][1]) * inv[mt][0];
                float p2 = ex2(s[mt][nt][2]) * inv[mt][1];
                float p3 = ex2(s[mt][nt][3]) * inv[mt][1];
                stg_cs2(pt + (size_t)g * SEQ + nt * 8 + i2,       p0, p1);
                stg_cs2(pt + (size_t)(8 + g) * SEQ + nt * 8 + i2, p2, p3);
            }
        }
        __syncthreads();
    }
}

extern "C" void kernel_launch(void* const* d_in, const int* in_sizes, int n_in,
                              void* d_out, int out_size) {
    const float* q = (const float*)d_in[0];
    const float* k = (const float*)d_in[1];
    const float* v = (const float*)d_in[2];
    float* out  = (float*)d_out;
    float* attn = out + (size_t)NBH * SEQ * HDIM;

    cudaFuncSetAttribute(attn_p1, cudaFuncAttributeMaxDynamicSharedMemorySize, SMEM_A);
    cudaFuncSetAttribute(attn_p2, cudaFuncAttributeMaxDynamicSharedMemorySize, SMEM_B);

    prep_kv<<<2048, 256>>>((const float4*)k, (const float4*)v);
    attn_p1<<<dim3(SEQ / QT, NBH), NTH, SMEM_A>>>(q, out);
    attn_p2<<<dim3(SEQ / QT, NBH), NTH, SMEM_B>>>(q, attn);
}

// round 14
// speedup vs baseline: 1.7007x; 1.7007x over previous
#include <cuda_runtime.h>
#include <cuda_fp16.h>
#include <cstdint>

#define SEQ 2048
#define HDIM 64
#define NBH 32
#define QT 64
#define KT 32
#define NTILES 64
#define NTH 64
// 0.125 * log2(e): scores computed directly in log2 domain
#define QSCALE2 0.18033688011112042f

// ---- kernel A smem: 2 KV buffers of 8KB; Q staging 8KB ----
#define BUFS 8192
#define KH_O 0
#define VH_O 4096
#define QH_A 16384
#define SMEM_A 24576
// ---- kernel B smem: 2 K buffers of 4KB; Q staging 8KB ----
#define QH_B 8192
#define SMEM_B 16384

__device__ __half g_kh[NBH*SEQ*HDIM];
__device__ __half g_vh[NBH*SEQ*HDIM];
__device__ float  g_inv[NBH*SEQ];

__device__ __forceinline__ uint32_t s2u(const void* p) {
    return (uint32_t)__cvta_generic_to_shared(p);
}
__device__ __forceinline__ void cp16(uint32_t dst, const void* src) {
    asm volatile("cp.async.cg.shared.global [%0], [%1], 16;" :: "r"(dst), "l"(src));
}
__device__ __forceinline__ void ldmx4(uint32_t* r, uint32_t a) {
    asm volatile("ldmatrix.sync.aligned.m8n8.x4.shared.b16 {%0,%1,%2,%3}, [%4];"
                 : "=r"(r[0]),"=r"(r[1]),"=r"(r[2]),"=r"(r[3]) : "r"(a));
}
__device__ __forceinline__ void ldmx4t(uint32_t* r, uint32_t a) {
    asm volatile("ldmatrix.sync.aligned.m8n8.x4.trans.shared.b16 {%0,%1,%2,%3}, [%4];"
                 : "=r"(r[0]),"=r"(r[1]),"=r"(r[2]),"=r"(r[3]) : "r"(a));
}
__device__ __forceinline__ void mma(float* c, const uint32_t* a, uint32_t b0, uint32_t b1) {
    asm volatile("mma.sync.aligned.m16n8k16.row.col.f32.f16.f16.f32 "
                 "{%0,%1,%2,%3}, {%4,%5,%6,%7}, {%8,%9}, {%0,%1,%2,%3};"
                 : "+f"(c[0]),"+f"(c[1]),"+f"(c[2]),"+f"(c[3])
                 : "r"(a[0]),"r"(a[1]),"r"(a[2]),"r"(a[3]), "r"(b0),"r"(b1));
}
__device__ __forceinline__ uint32_t h2pk(float a, float b) {
    uint32_t r;
    asm("cvt.rn.f16x2.f32 %0, %1, %2;" : "=r"(r) : "f"(b), "f"(a));
    return r;
}
__device__ __forceinline__ float ex2(float x) {
    float r;
    asm("ex2.approx.f32 %0, %1;" : "=f"(r) : "f"(x));
    return r;
}
// swizzled byte offset within a [rows x 128B] fp16 tile (16B unit c = 0..7)
__device__ __forceinline__ uint32_t swz(int row, int c) {
    return (uint32_t)row * 128u + (uint32_t)(((c ^ (row & 7)) & 7) << 4);
}

// load K+V fp16 for one 32-key tile (8KB, 512 cp16, 8 each)
__device__ __forceinline__ void ldtileKV(uint32_t sb, int buf, int tile, int bh, int tid) {
    size_t base = ((size_t)bh * SEQ + (size_t)tile * KT) * HDIM;
    uint32_t bo = sb + (uint32_t)buf * BUFS;
    #pragma unroll
    for (int m = 0; m < 8; m++) {
        int e = tid + (m & 3) * NTH;
        int row = e >> 3, c = e & 7;
        const __half* s = (m < 4) ? g_kh : g_vh;
        cp16(bo + (uint32_t)(m >> 2) * 4096u + swz(row, c),
             s + base + row * HDIM + c * 8);
    }
}
// load K only into 4KB buffer (256 cp16, 4 each)
__device__ __forceinline__ void ldtileK(uint32_t sb, int buf, int tile, int bh, int tid) {
    size_t base = ((size_t)bh * SEQ + (size_t)tile * KT) * HDIM;
    uint32_t bo = sb + (uint32_t)buf * 4096u;
    #pragma unroll
    for (int m = 0; m < 4; m++) {
        int e = tid + m * NTH;
        int row = e >> 3, c = e & 7;
        cp16(bo + swz(row, c), g_kh + base + row * HDIM + c * 8);
    }
}
// stage 64 rows of Q (scaled fp16) into smem at offset qo
__device__ __forceinline__ void stageQ(char* smem, uint32_t qo,
                                       const float* __restrict__ Qg,
                                       int bh, int q0, int tid) {
    #pragma unroll
    for (int i = 0; i < 8; i++) {
        int gid = tid + i * NTH;
        int row = gid >> 3, c = gid & 7;
        const float* qp = Qg + ((size_t)(bh * SEQ + q0 + row)) * HDIM + c * 8;
        float4 f0 = *(const float4*)qp, f1 = *(const float4*)(qp + 4);
        uint32_t h[4];
        h[0] = h2pk(f0.x * QSCALE2, f0.y * QSCALE2);
        h[1] = h2pk(f0.z * QSCALE2, f0.w * QSCALE2);
        h[2] = h2pk(f1.x * QSCALE2, f1.y * QSCALE2);
        h[3] = h2pk(f1.z * QSCALE2, f1.w * QSCALE2);
        *(uint4*)(smem + qo + swz(row, c)) = make_uint4(h[0], h[1], h[2], h[3]);
    }
}

__global__ void prep_kv(const float4* __restrict__ K4, const float4* __restrict__ V4) {
    const int n4 = NBH * SEQ * HDIM / 4;
    uint2* kh = (uint2*)g_kh;
    uint2* vh = (uint2*)g_vh;
    for (int i = blockIdx.x * blockDim.x + threadIdx.x; i < n4; i += gridDim.x * blockDim.x) {
        float4 k = K4[i];
        kh[i] = make_uint2(h2pk(k.x, k.y), h2pk(k.z, k.w));
        float4 v = V4[i];
        vh[i] = make_uint2(h2pk(v.x, v.y), h2pk(v.z, v.w));
    }
}

// =============== KERNEL A: O + rowsum -> inv ===============
__global__ __launch_bounds__(NTH, 6)
void attn_p1(const float* __restrict__ Qg, float* __restrict__ Og) {
    extern __shared__ char smem[];
    const int tid = threadIdx.x, wid = tid >> 5, L = tid & 31;
    const int bh = blockIdx.y, q0 = blockIdx.x * QT;
    const uint32_t sb = s2u(smem);

    ldtileKV(sb, 0, 0, bh, tid);
    asm volatile("cp.async.commit_group;" ::: "memory");
    stageQ(smem, QH_A, Qg, bh, q0, tid);
    __syncthreads();

    const int g = L >> 2, i2 = (L & 3) * 2;
    const int qc_sel  = L >> 4;
    const int rk_base = (L & 7) + ((L >> 4) << 3);
    const int ck_sel  = (L >> 3) & 1;
    const int rv_base = (L & 7) + (((L >> 3) & 1) << 3);
    const int cv_sel  = L >> 4;

    // Q A-fragments in registers: [mt][ks], reused by all 64 tiles
    uint32_t qf[2][4][4];
    #pragma unroll
    for (int mt = 0; mt < 2; mt++) {
        int qrow = wid * 32 + mt * 16 + (L & 7) + (((L >> 3) & 1) << 3);
        #pragma unroll
        for (int ks = 0; ks < 4; ks++)
            ldmx4(qf[mt][ks], sb + QH_A + swz(qrow, 2 * ks + qc_sel));
    }

    float o[2][8][4];
    #pragma unroll
    for (int mt = 0; mt < 2; mt++)
        #pragma unroll
        for (int i = 0; i < 8; i++)
            #pragma unroll
            for (int j = 0; j < 4; j++) o[mt][i][j] = 0.f;
    float rs[2][2] = {{0.f, 0.f}, {0.f, 0.f}};

    for (int t = 0; t < NTILES; t++) {
        if (t + 1 < NTILES) {
            ldtileKV(sb, (t + 1) & 1, t + 1, bh, tid);
            asm volatile("cp.async.commit_group;" ::: "memory");
            asm volatile("cp.async.wait_group 1;" ::: "memory");
        } else {
            asm volatile("cp.async.wait_group 0;" ::: "memory");
        }
        __syncthreads();
        const uint32_t kb = sb + (uint32_t)(t & 1) * BUFS;

        float s[2][4][4];
        #pragma unroll
        for (int mt = 0; mt < 2; mt++)
            #pragma unroll
            for (int i = 0; i < 4; i++)
                #pragma unroll
                for (int j = 0; j < 4; j++) s[mt][i][j] = 0.f;

        #pragma unroll
        for (int ks = 0; ks < 4; ks++) {
            int ck = 2 * ks + ck_sel;
            #pragma unroll
            for (int ntp = 0; ntp < 2; ntp++) {
                uint32_t bf[4];
                ldmx4(bf, kb + KH_O + swz(ntp * 16 + rk_base, ck));
                #pragma unroll
                for (int mt = 0; mt < 2; mt++) {
                    mma(s[mt][2*ntp],   qf[mt][ks], bf[0], bf[1]);
                    mma(s[mt][2*ntp+1], qf[mt][ks], bf[2], bf[3]);
                }
            }
        }

        uint32_t pah[2][2][4];
        #pragma unroll
        for (int mt = 0; mt < 2; mt++)
            #pragma unroll
            for (int nt = 0; nt < 4; nt++) {
                float p0 = ex2(s[mt][nt][0]), p1 = ex2(s[mt][nt][1]);
                float p2 = ex2(s[mt][nt][2]), p3 = ex2(s[mt][nt][3]);
                rs[mt][0] += p0 + p1; rs[mt][1] += p2 + p3;
                pah[mt][nt >> 1][(nt & 1) * 2 + 0] = h2pk(p0, p1);
                pah[mt][nt >> 1][(nt & 1) * 2 + 1] = h2pk(p2, p3);
            }

        #pragma unroll
        for (int ks = 0; ks < 2; ks++) {
            int rv = ks * 16 + rv_base;
            #pragma unroll
            for (int dp = 0; dp < 4; dp++) {
                uint32_t vh[4];
                ldmx4t(vh, kb + VH_O + swz(rv, dp * 2 + cv_sel));
                #pragma unroll
                for (int mt = 0; mt < 2; mt++) {
                    mma(o[mt][2*dp],   pah[mt][ks], vh[0], vh[1]);
                    mma(o[mt][2*dp+1], pah[mt][ks], vh[2], vh[3]);
                }
            }
        }
        __syncthreads();
    }

    float inv[2][2];
    #pragma unroll
    for (int mt = 0; mt < 2; mt++)
        #pragma unroll
        for (int j = 0; j < 2; j++) {
            float r = rs[mt][j];
            r += __shfl_xor_sync(0xFFFFFFFFu, r, 1);
            r += __shfl_xor_sync(0xFFFFFFFFu, r, 2);
            inv[mt][j] = 1.0f / r;
        }

    #pragma unroll
    for (int mt = 0; mt < 2; mt++) {
        if ((L & 3) == 0) {
            g_inv[bh * SEQ + q0 + wid * 32 + mt * 16 + g]     = inv[mt][0];
            g_inv[bh * SEQ + q0 + wid * 32 + mt * 16 + 8 + g] = inv[mt][1];
        }
        float* ob = Og + ((size_t)(bh * SEQ + q0 + wid * 32 + mt * 16)) * HDIM;
        #pragma unroll
        for (int nt = 0; nt < 8; nt++) {
            *(float2*)(ob + (size_t)g * HDIM + nt * 8 + i2) =
                make_float2(o[mt][nt][0] * inv[mt][0], o[mt][nt][1] * inv[mt][0]);
            *(float2*)(ob + (size_t)(8 + g) * HDIM + nt * 8 + i2) =
                make_float2(o[mt][nt][2] * inv[mt][1], o[mt][nt][3] * inv[mt][1]);
        }
    }
}

// =============== KERNEL B: recompute scores, store normalized P ===============
__global__ __launch_bounds__(NTH, 10)
void attn_p2(const float* __restrict__ Qg, float* __restrict__ Pg) {
    extern __shared__ char smem[];
    const int tid = threadIdx.x, wid = tid >> 5, L = tid & 31;
    const int bh = blockIdx.y, q0 = blockIdx.x * QT;
    const uint32_t sb = s2u(smem);

    ldtileK(sb, 0, 0, bh, tid);
    asm volatile("cp.async.commit_group;" ::: "memory");
    stageQ(smem, QH_B, Qg, bh, q0, tid);
    __syncthreads();

    const int g = L >> 2, i2 = (L & 3) * 2;
    const int qc_sel  = L >> 4;
    const int rk_base = (L & 7) + ((L >> 4) << 3);
    const int ck_sel  = (L >> 3) & 1;

    uint32_t qf[2][4][4];
    #pragma unroll
    for (int mt = 0; mt < 2; mt++) {
        int qrow = wid * 32 + mt * 16 + (L & 7) + (((L >> 3) & 1) << 3);
        #pragma unroll
        for (int ks = 0; ks < 4; ks++)
            ldmx4(qf[mt][ks], sb + QH_B + swz(qrow, 2 * ks + qc_sel));
    }

    float inv[2][2];
    #pragma unroll
    for (int mt = 0; mt < 2; mt++) {
        inv[mt][0] = g_inv[bh * SEQ + q0 + wid * 32 + mt * 16 + g];
        inv[mt][1] = g_inv[bh * SEQ + q0 + wid * 32 + mt * 16 + 8 + g];
    }

    for (int t = 0; t < NTILES; t++) {
        if (t + 1 < NTILES) {
            ldtileK(sb, (t + 1) & 1, t + 1, bh, tid);
            asm volatile("cp.async.commit_group;" ::: "memory");
            asm volatile("cp.async.wait_group 1;" ::: "memory");
        } else {
            asm volatile("cp.async.wait_group 0;" ::: "memory");
        }
        __syncthreads();
        const uint32_t kb = sb + (uint32_t)(t & 1) * 4096u;

        float s[2][4][4];
        #pragma unroll
        for (int mt = 0; mt < 2; mt++)
            #pragma unroll
            for (int i = 0; i < 4; i++)
                #pragma unroll
                for (int j = 0; j < 4; j++) s[mt][i][j] = 0.f;

        #pragma unroll
        for (int ks = 0; ks < 4; ks++) {
            int ck = 2 * ks + ck_sel;
            #pragma unroll
            for (int ntp = 0; ntp < 2; ntp++) {
                uint32_t bf[4];
                ldmx4(bf, kb + swz(ntp * 16 + rk_base, ck));
                #pragma unroll
                for (int mt = 0; mt < 2; mt++) {
                    mma(s[mt][2*ntp],   qf[mt][ks], bf[0], bf[1]);
                    mma(s[mt][2*ntp+1], qf[mt][ks], bf[2], bf[3]);
                }
            }
        }

        #pragma unroll
        for (int mt = 0; mt < 2; mt++) {
            float* pt = Pg + ((size_t)(bh * SEQ + q0 + wid * 32 + mt * 16)) * SEQ
                        + (size_t)t * KT;
            #pragma unroll
            for (int nt = 0; nt < 4; nt++) {
                float p0 = ex2(s[mt][nt][0]) * inv[mt][0];
                float p1 = ex2(s[mt][nt][1]) * inv[mt][0];
                float p2 = ex2(s[mt][nt][2]) * inv[mt][1];
                float p3 = ex2(s[mt][nt][3]) * inv[mt][1];
                *(float2*)(pt + (size_t)g * SEQ + nt * 8 + i2)       = make_float2(p0, p1);
                *(float2*)(pt + (size_t)(8 + g) * SEQ + nt * 8 + i2) = make_float2(p2, p3);
            }
        }
        __syncthreads();
    }
}

extern "C" void kernel_launch(void* const* d_in, const int* in_sizes, int n_in,
                              void* d_out, int out_size) {
    const float* q = (const float*)d_in[0];
    const float* k = (const float*)d_in[1];
    const float* v = (const float*)d_in[2];
    float* out  = (float*)d_out;
    float* attn = out + (size_t)NBH * SEQ * HDIM;

    cudaFuncSetAttribute(attn_p1, cudaFuncAttributeMaxDynamicSharedMemorySize, SMEM_A);
    cudaFuncSetAttribute(attn_p2, cudaFuncAttributeMaxDynamicSharedMemorySize, SMEM_B);

    prep_kv<<<2048, 256>>>((const float4*)k, (const float4*)v);
    attn_p1<<<dim3(SEQ / QT, NBH), NTH, SMEM_A>>>(q, out);
    attn_p2<<<dim3(SEQ / QT, NBH), NTH, SMEM_B>>>(q, attn);
}

// round 17
// speedup vs baseline: 1.8891x; 1.1108x over previous
#include <cuda_runtime.h>
#include <cuda_fp16.h>
#include <cstdint>

#define SEQ 2048
#define HDIM 64
#define NBH 32
#define QT 64
#define KT 32
#define NTILES 64
#define NTH1 128
#define NTH2 64
// 0.125 * log2(e): scores computed directly in log2 domain
#define QSCALE2 0.18033688011112042f

// ---- kernel A smem: 2 KV buffers of 8KB; Q staging 8KB ----
#define BUFS 8192
#define KH_O 0
#define VH_O 4096
#define QH_A 16384
#define SMEM_A 24576
// ---- kernel B smem: 2 K buffers of 4KB; Q staging 8KB ----
#define QH_B 8192
#define SMEM_B 16384

__device__ __half g_kh[NBH*SEQ*HDIM];
__device__ __half g_vh[NBH*SEQ*HDIM];
__device__ float  g_inv[NBH*SEQ];

__device__ __forceinline__ uint32_t s2u(const void* p) {
    return (uint32_t)__cvta_generic_to_shared(p);
}
__device__ __forceinline__ void cp16(uint32_t dst, const void* src) {
    asm volatile("cp.async.cg.shared.global [%0], [%1], 16;" :: "r"(dst), "l"(src));
}
__device__ __forceinline__ void ldmx4(uint32_t* r, uint32_t a) {
    asm volatile("ldmatrix.sync.aligned.m8n8.x4.shared.b16 {%0,%1,%2,%3}, [%4];"
                 : "=r"(r[0]),"=r"(r[1]),"=r"(r[2]),"=r"(r[3]) : "r"(a));
}
__device__ __forceinline__ void ldmx4t(uint32_t* r, uint32_t a) {
    asm volatile("ldmatrix.sync.aligned.m8n8.x4.trans.shared.b16 {%0,%1,%2,%3}, [%4];"
                 : "=r"(r[0]),"=r"(r[1]),"=r"(r[2]),"=r"(r[3]) : "r"(a));
}
__device__ __forceinline__ void mma(float* c, const uint32_t* a, uint32_t b0, uint32_t b1) {
    asm volatile("mma.sync.aligned.m16n8k16.row.col.f32.f16.f16.f32 "
                 "{%0,%1,%2,%3}, {%4,%5,%6,%7}, {%8,%9}, {%0,%1,%2,%3};"
                 : "+f"(c[0]),"+f"(c[1]),"+f"(c[2]),"+f"(c[3])
                 : "r"(a[0]),"r"(a[1]),"r"(a[2]),"r"(a[3]), "r"(b0),"r"(b1));
}
__device__ __forceinline__ uint32_t h2pk(float a, float b) {
    uint32_t r;
    asm("cvt.rn.f16x2.f32 %0, %1, %2;" : "=r"(r) : "f"(b), "f"(a));
    return r;
}
__device__ __forceinline__ float ex2(float x) {
    float r;
    asm("ex2.approx.f32 %0, %1;" : "=f"(r) : "f"(x));
    return r;
}
// swizzled byte offset within a [rows x 128B] fp16 tile (16B unit c = 0..7)
__device__ __forceinline__ uint32_t swz(int row, int c) {
    return (uint32_t)row * 128u + (uint32_t)(((c ^ (row & 7)) & 7) << 4);
}

// load K+V fp16 for one 32-key tile (8KB = 512 cp16 total), NT = threads
template<int NT>
__device__ __forceinline__ void ldtileKV(uint32_t sb, int buf, int tile, int bh, int tid) {
    size_t base = ((size_t)bh * SEQ + (size_t)tile * KT) * HDIM;
    uint32_t bo = sb + (uint32_t)buf * BUFS;
    #pragma unroll
    for (int m = 0; m < 512 / NT; m++) {
        int idx = tid + m * NT;           // 0..511
        int e = idx & 255;
        int half = (idx >> 8) & 1;        // 0 = K, 1 = V
        int row = e >> 3, c = e & 7;
        const __half* s = half ? g_vh : g_kh;
        cp16(bo + (uint32_t)half * 4096u + swz(row, c),
             s + base + row * HDIM + c * 8);
    }
}
// load K only into 4KB buffer (256 cp16 total)
template<int NT>
__device__ __forceinline__ void ldtileK(uint32_t sb, int buf, int tile, int bh, int tid) {
    size_t base = ((size_t)bh * SEQ + (size_t)tile * KT) * HDIM;
    uint32_t bo = sb + (uint32_t)buf * 4096u;
    #pragma unroll
    for (int m = 0; m < 256 / NT; m++) {
        int e = tid + m * NT;
        int row = e >> 3, c = e & 7;
        cp16(bo + swz(row, c), g_kh + base + row * HDIM + c * 8);
    }
}
// stage 64 rows of Q (scaled fp16) into smem at offset qo (512 uint4 total)
template<int NT>
__device__ __forceinline__ void stageQ(char* smem, uint32_t qo,
                                       const float* __restrict__ Qg,
                                       int bh, int q0, int tid) {
    #pragma unroll
    for (int i = 0; i < 512 / NT; i++) {
        int gid = tid + i * NT;
        int row = gid >> 3, c = gid & 7;
        const float* qp = Qg + ((size_t)(bh * SEQ + q0 + row)) * HDIM + c * 8;
        float4 f0 = *(const float4*)qp, f1 = *(const float4*)(qp + 4);
        uint32_t h[4];
        h[0] = h2pk(f0.x * QSCALE2, f0.y * QSCALE2);
        h[1] = h2pk(f0.z * QSCALE2, f0.w * QSCALE2);
        h[2] = h2pk(f1.x * QSCALE2, f1.y * QSCALE2);
        h[3] = h2pk(f1.z * QSCALE2, f1.w * QSCALE2);
        *(uint4*)(smem + qo + swz(row, c)) = make_uint4(h[0], h[1], h[2], h[3]);
    }
}

__global__ void prep_kv(const float4* __restrict__ K4, const float4* __restrict__ V4) {
    const int n4 = NBH * SEQ * HDIM / 4;
    uint2* kh = (uint2*)g_kh;
    uint2* vh = (uint2*)g_vh;
    for (int i = blockIdx.x * blockDim.x + threadIdx.x; i < n4; i += gridDim.x * blockDim.x) {
        float4 k = K4[i];
        kh[i] = make_uint2(h2pk(k.x, k.y), h2pk(k.z, k.w));
        float4 v = V4[i];
        vh[i] = make_uint2(h2pk(v.x, v.y), h2pk(v.z, v.w));
    }
}

// =============== KERNEL A: O + rowsum -> inv (4 warps x 16 q-rows) ===============
__global__ __launch_bounds__(NTH1, 4)
void attn_p1(const float* __restrict__ Qg, float* __restrict__ Og) {
    extern __shared__ char smem[];
    const int tid = threadIdx.x, wid = tid >> 5, L = tid & 31;
    const int bh = blockIdx.y, q0 = blockIdx.x * QT;
    const uint32_t sb = s2u(smem);

    ldtileKV<NTH1>(sb, 0, 0, bh, tid);
    asm volatile("cp.async.commit_group;" ::: "memory");
    stageQ<NTH1>(smem, QH_A, Qg, bh, q0, tid);
    __syncthreads();

    const int g = L >> 2, i2 = (L & 3) * 2;
    const int qc_sel  = L >> 4;
    const int rk_base = (L & 7) + ((L >> 4) << 3);
    const int ck_sel  = (L >> 3) & 1;
    const int rv_base = (L & 7) + (((L >> 3) & 1) << 3);
    const int cv_sel  = L >> 4;

    // Q A-fragments in registers: warp owns 16 q-rows
    uint32_t qf[4][4];
    {
        int qrow = wid * 16 + (L & 7) + (((L >> 3) & 1) << 3);
        #pragma unroll
        for (int ks = 0; ks < 4; ks++)
            ldmx4(qf[ks], sb + QH_A + swz(qrow, 2 * ks + qc_sel));
    }

    float o[8][4];
    #pragma unroll
    for (int i = 0; i < 8; i++)
        #pragma unroll
        for (int j = 0; j < 4; j++) o[i][j] = 0.f;
    float rs0 = 0.f, rs1 = 0.f;

    for (int t = 0; t < NTILES; t++) {
        if (t + 1 < NTILES) {
            ldtileKV<NTH1>(sb, (t + 1) & 1, t + 1, bh, tid);
            asm volatile("cp.async.commit_group;" ::: "memory");
            asm volatile("cp.async.wait_group 1;" ::: "memory");
        } else {
            asm volatile("cp.async.wait_group 0;" ::: "memory");
        }
        __syncthreads();
        const uint32_t kb = sb + (uint32_t)(t & 1) * BUFS;

        float s[4][4];
        #pragma unroll
        for (int i = 0; i < 4; i++)
            #pragma unroll
            for (int j = 0; j < 4; j++) s[i][j] = 0.f;

        #pragma unroll
        for (int ks = 0; ks < 4; ks++) {
            int ck = 2 * ks + ck_sel;
            #pragma unroll
            for (int ntp = 0; ntp < 2; ntp++) {
                uint32_t bf[4];
                ldmx4(bf, kb + KH_O + swz(ntp * 16 + rk_base, ck));
                mma(s[2*ntp],   qf[ks], bf[0], bf[1]);
                mma(s[2*ntp+1], qf[ks], bf[2], bf[3]);
            }
        }

        uint32_t pah[2][4];
        #pragma unroll
        for (int nt = 0; nt < 4; nt++) {
            float p0 = ex2(s[nt][0]), p1 = ex2(s[nt][1]);
            float p2 = ex2(s[nt][2]), p3 = ex2(s[nt][3]);
            rs0 += p0 + p1; rs1 += p2 + p3;
            pah[nt >> 1][(nt & 1) * 2 + 0] = h2pk(p0, p1);
            pah[nt >> 1][(nt & 1) * 2 + 1] = h2pk(p2, p3);
        }

        #pragma unroll
        for (int ks = 0; ks < 2; ks++) {
            int rv = ks * 16 + rv_base;
            #pragma unroll
            for (int dp = 0; dp < 4; dp++) {
                uint32_t vh[4];
                ldmx4t(vh, kb + VH_O + swz(rv, dp * 2 + cv_sel));
                mma(o[2*dp],   pah[ks], vh[0], vh[1]);
                mma(o[2*dp+1], pah[ks], vh[2], vh[3]);
            }
        }
        __syncthreads();
    }

    rs0 += __shfl_xor_sync(0xFFFFFFFFu, rs0, 1);
    rs0 += __shfl_xor_sync(0xFFFFFFFFu, rs0, 2);
    rs1 += __shfl_xor_sync(0xFFFFFFFFu, rs1, 1);
    rs1 += __shfl_xor_sync(0xFFFFFFFFu, rs1, 2);
    const float inv0 = 1.0f / rs0, inv1 = 1.0f / rs1;

    if ((L & 3) == 0) {
        g_inv[bh * SEQ + q0 + wid * 16 + g]     = inv0;
        g_inv[bh * SEQ + q0 + wid * 16 + 8 + g] = inv1;
    }
    {
        float* ob = Og + ((size_t)(bh * SEQ + q0 + wid * 16)) * HDIM;
        #pragma unroll
        for (int nt = 0; nt < 8; nt++) {
            *(float2*)(ob + (size_t)g * HDIM + nt * 8 + i2) =
                make_float2(o[nt][0] * inv0, o[nt][1] * inv0);
            *(float2*)(ob + (size_t)(8 + g) * HDIM + nt * 8 + i2) =
                make_float2(o[nt][2] * inv1, o[nt][3] * inv1);
        }
    }
}

// =============== KERNEL B: recompute scores, store normalized P ===============
__global__ __launch_bounds__(NTH2, 10)
void attn_p2(const float* __restrict__ Qg, float* __restrict__ Pg) {
    extern __shared__ char smem[];
    const int tid = threadIdx.x, wid = tid >> 5, L = tid & 31;
    const int bh = blockIdx.y, q0 = blockIdx.x * QT;
    const uint32_t sb = s2u(smem);

    ldtileK<NTH2>(sb, 0, 0, bh, tid);
    asm volatile("cp.async.commit_group;" ::: "memory");
    stageQ<NTH2>(smem, QH_B, Qg, bh, q0, tid);
    __syncthreads();

    const int g = L >> 2, i2 = (L & 3) * 2;
    const int qc_sel  = L >> 4;
    const int rk_base = (L & 7) + ((L >> 4) << 3);
    const int ck_sel  = (L >> 3) & 1;

    uint32_t qf[2][4][4];
    #pragma unroll
    for (int mt = 0; mt < 2; mt++) {
        int qrow = wid * 32 + mt * 16 + (L & 7) + (((L >> 3) & 1) << 3);
        #pragma unroll
        for (int ks = 0; ks < 4; ks++)
            ldmx4(qf[mt][ks], sb + QH_B + swz(qrow, 2 * ks + qc_sel));
    }

    float inv[2][2];
    #pragma unroll
    for (int mt = 0; mt < 2; mt++) {
        inv[mt][0] = g_inv[bh * SEQ + q0 + wid * 32 + mt * 16 + g];
        inv[mt][1] = g_inv[bh * SEQ + q0 + wid * 32 + mt * 16 + 8 + g];
    }

    for (int t = 0; t < NTILES; t++) {
        if (t + 1 < NTILES) {
            ldtileK<NTH2>(sb, (t + 1) & 1, t + 1, bh, tid);
            asm volatile("cp.async.commit_group;" ::: "memory");
            asm volatile("cp.async.wait_group 1;" ::: "memory");
        } else {
            asm volatile("cp.async.wait_group 0;" ::: "memory");
        }
        __syncthreads();
        const uint32_t kb = sb + (uint32_t)(t & 1) * 4096u;

        float s[2][4][4];
        #pragma unroll
        for (int mt = 0; mt < 2; mt++)
            #pragma unroll
            for (int i = 0; i < 4; i++)
                #pragma unroll
                for (int j = 0; j < 4; j++) s[mt][i][j] = 0.f;

        #pragma unroll
        for (int ks = 0; ks < 4; ks++) {
            int ck = 2 * ks + ck_sel;
            #pragma unroll
            for (int ntp = 0; ntp < 2; ntp++) {
                uint32_t bf[4];
                ldmx4(bf, kb + swz(ntp * 16 + rk_base, ck));
                #pragma unroll
                for (int mt = 0; mt < 2; mt++) {
                    mma(s[mt][2*ntp],   qf[mt][ks], bf[0], bf[1]);
                    mma(s[mt][2*ntp+1], qf[mt][ks], bf[2], bf[3]);
                }
            }
        }

        #pragma unroll
        for (int mt = 0; mt < 2; mt++) {
            float* pt = Pg + ((size_t)(bh * SEQ + q0 + wid * 32 + mt * 16)) * SEQ
                        + (size_t)t * KT;
            #pragma unroll
            for (int nt = 0; nt < 4; nt++) {
                float p0 = ex2(s[mt][nt][0]) * inv[mt][0];
                float p1 = ex2(s[mt][nt][1]) * inv[mt][0];
                float p2 = ex2(s[mt][nt][2]) * inv[mt][1];
                float p3 = ex2(s[mt][nt][3]) * inv[mt][1];
                *(float2*)(pt + (size_t)g * SEQ + nt * 8 + i2)       = make_float2(p0, p1);
                *(float2*)(pt + (size_t)(8 + g) * SEQ + nt * 8 + i2) = make_float2(p2, p3);
            }
        }
        __syncthreads();
    }
}

extern "C" void kernel_launch(void* const* d_in, const int* in_sizes, int n_in,
                              void* d_out, int out_size) {
    const float* q = (const float*)d_in[0];
    const float* k = (const float*)d_in[1];
    const float* v = (const float*)d_in[2];
    float* out  = (float*)d_out;
    float* attn = out + (size_t)NBH * SEQ * HDIM;

    cudaFuncSetAttribute(attn_p1, cudaFuncAttributeMaxDynamicSharedMemorySize, SMEM_A);
    cudaFuncSetAttribute(attn_p2, cudaFuncAttributeMaxDynamicSharedMemorySize, SMEM_B);

    prep_kv<<<2048, 256>>>((const float4*)k, (const float4*)v);
    attn_p1<<<dim3(SEQ / QT, NBH), NTH1, SMEM_A>>>(q, out);
    attn_p2<<<dim3(SEQ / QT, NBH), NTH2, SMEM_B>>>(q, attn);
}